// round 15
// baseline (speedup 1.0000x reference)
#include <cuda_runtime.h>
#include <math.h>

#define MAX_NODES 100000
#define NGRAPH    32

// Self-cleaning scratch: zero at module load; each kernel that consumes a
// buffer re-zeroes it for the next graph replay.
static __device__ float2 g_nd[MAX_NODES];        // {density, rep} per node
static __device__ float  g_coef[MAX_NODES];      // dE/d(local_density) per node
static __device__ float4 g_f4[MAX_NODES];        // padded force accumulators
static __device__ float  g_enode[NGRAPH];
static __device__ float  g_eedge[NGRAPH];

__device__ __forceinline__ float softplus_f(float x) {
    return (x > 20.0f) ? x : log1pf(__expf(x));
}

__device__ __forceinline__ void red_add_v2(float2* p, float x, float y) {
    asm volatile("red.global.add.v2.f32 [%0], {%1, %2};"
                 :: "l"(p), "f"(x), "f"(y)
                 : "memory");
}

__device__ __forceinline__ void red_add_v4(float4* p, float x, float y, float z) {
    asm volatile("red.global.add.v4.f32 [%0], {%1, %2, %3, %4};"
                 :: "l"(p), "f"(x), "f"(y), "f"(z), "f"(0.0f)
                 : "memory");
}

// ---------------- forward: fused {density, rep} scatter ---------------------
// e_edge(g) factors through per-node rep sums, so rep rides in the same
// per-node vector RED as density (no per-edge graph atomic / n2g gather).
// LOCKED: 4 edges/thread (8/thread measured worse — RED-throughput bound).
__device__ __forceinline__ void fwd_one(float rx, float ry, float rz, int d,
                                        float Ad, float Ld, float Ar, float Lr) {
    float b = sqrtf(rx * rx + ry * ry + rz * rz);
    float dens = Ad * __expf(-Ld * b);
    float rep  = Ar * __expf(-Lr * b);
    red_add_v2(&g_nd[d], dens, rep);
}

__global__ void __launch_bounds__(256, 6)
k_edge_fwd(const float* __restrict__ r,
           const int*   __restrict__ dst,
           const float* __restrict__ pAd, const float* __restrict__ pLd,
           const float* __restrict__ pAr, const float* __restrict__ pLr,
           int E) {
    const float Ad = softplus_f(__ldg(pAd));
    const float Ld = softplus_f(__ldg(pLd));
    const float Ar = softplus_f(__ldg(pAr));
    const float Lr = softplus_f(__ldg(pLr));

    const int nq = E >> 2;
    const int q  = blockIdx.x * blockDim.x + threadIdx.x;

    const float4* r4 = (const float4*)r;
    const int4*   d4 = (const int4*)dst;

    if (q < nq) {
        float4 A = __ldg(r4 + 3 * q + 0);
        float4 B = __ldg(r4 + 3 * q + 1);
        float4 C = __ldg(r4 + 3 * q + 2);
        int4   D = __ldg(d4 + q);
        fwd_one(A.x, A.y, A.z, D.x, Ad, Ld, Ar, Lr);
        fwd_one(A.w, B.x, B.y, D.y, Ad, Ld, Ar, Lr);
        fwd_one(B.z, B.w, C.x, D.z, Ad, Ld, Ar, Lr);
        fwd_one(C.y, C.z, C.w, D.w, Ad, Ld, Ar, Lr);
    }
    // tail edges (E not divisible by 4) handled by first threads
    int t = q - nq;
    int e = 4 * nq + t;
    if (t >= 0 && e < E) {
        fwd_one(__ldg(r + 3 * e), __ldg(r + 3 * e + 1), __ldg(r + 3 * e + 2),
                __ldg(dst + e), Ad, Ld, Ar, Lr);
    }
}

// ---------------- node pass: embedding, grad coef, graph readouts -----------
// Two nodes per thread: one float4 load covers two g_nd entries, one float2
// store writes both coefs, and (node2graph is sorted) paired nodes nearly
// always share a graph -> combined smem atomic per pair.
__global__ void k_node(const int* __restrict__ n2g,
                       const float* __restrict__ pAe,
                       int N) {
    __shared__ float sF[NGRAPH];
    __shared__ float sR[NGRAPH];
    if (threadIdx.x < NGRAPH) { sF[threadIdx.x] = 0.0f; sR[threadIdx.x] = 0.0f; }
    __syncthreads();

    const float Ae = softplus_f(__ldg(pAe));
    int t  = blockIdx.x * blockDim.x + threadIdx.x;
    int i0 = 2 * t;
    if (i0 < N) {
        const float4* nd4 = (const float4*)g_nd;
        bool pair = (i0 + 1 < N);
        float4 v;
        if (pair) {
            v = nd4[t];                       // {ld0, rep0, ld1, rep1}
        } else {
            float2 s = g_nd[i0];
            v = make_float4(s.x, s.y, 0.0f, 0.0f);
        }

        float F0, c0, F1 = 0.0f, c1 = 0.0f;
        {
            float ld = v.x;
            if (ld > 1e-12f) {
                float rs = rsqrtf(ld);
                F0 = -Ae * ld * rs; c0 = -0.5f * Ae * rs;
            } else { F0 = -Ae * 1e-6f; c0 = 0.0f; }
        }
        if (pair) {
            float ld = v.z;
            if (ld > 1e-12f) {
                float rs = rsqrtf(ld);
                F1 = -Ae * ld * rs; c1 = -0.5f * Ae * rs;
            } else { F1 = -Ae * 1e-6f; c1 = 0.0f; }
        }

        // write both coefs with one 8B store; self-clean g_nd with one 16B store
        if (pair) {
            ((float2*)g_coef)[t] = make_float2(c0, c1);
            ((float4*)g_nd)[t]   = make_float4(0.0f, 0.0f, 0.0f, 0.0f);
        } else {
            g_coef[i0] = c0;
            g_nd[i0]   = make_float2(0.0f, 0.0f);
        }

        int g0 = __ldg(n2g + i0);
        int g1 = pair ? __ldg(n2g + i0 + 1) : g0;
        float rep1 = pair ? v.w : 0.0f;
        if (g0 == g1) {                        // common case: sorted n2g
            atomicAdd(&sF[g0], F0 + F1);
            atomicAdd(&sR[g0], v.y + rep1);
        } else {
            atomicAdd(&sF[g0], F0);
            atomicAdd(&sR[g0], v.y);
            atomicAdd(&sF[g1], F1);
            atomicAdd(&sR[g1], rep1);
        }
    }

    __syncthreads();
    if (threadIdx.x < NGRAPH) {
        atomicAdd(&g_enode[threadIdx.x], sF[threadIdx.x]);
        atomicAdd(&g_eedge[threadIdx.x], sR[threadIdx.x]);
    }
}

// ---------------- backward: force scatter -----------------------------------
__device__ __forceinline__ void bwd_one(float rx, float ry, float rz,
                                        int d, int s, float c,
                                        float Ad, float Ld, float Ar, float Lr) {
    float b2    = rx * rx + ry * ry + rz * rz;
    float inv_b = rsqrtf(b2);
    float b     = b2 * inv_b;
    float dens  = Ad * __expf(-Ld * b);
    float rep   = Ar * __expf(-Lr * b);
    float dEdb  = -c * Ld * dens - Lr * rep;
    float scale = dEdb * inv_b;
    float dx = scale * rx, dy = scale * ry, dz = scale * rz;
    red_add_v4(&g_f4[d], -dx, -dy, -dz);
    red_add_v4(&g_f4[s],  dx,  dy,  dz);
}

// One octet (8 edges) per thread; block->edge mapping REVERSED so the first
// bwd wave touches the tail of r/src/dst that k_edge_fwd left in L2.
__global__ void __launch_bounds__(256, 6)
k_edge_bwd(const float* __restrict__ r,
           const int*   __restrict__ src,
           const int*   __restrict__ dst,
           const float* __restrict__ pAd, const float* __restrict__ pLd,
           const float* __restrict__ pAr, const float* __restrict__ pLr,
           int E) {
    const float Ad = softplus_f(__ldg(pAd));
    const float Ld = softplus_f(__ldg(pLd));
    const float Ar = softplus_f(__ldg(pAr));
    const float Lr = softplus_f(__ldg(pLr));

    const int no  = E >> 3;
    const int tid = blockIdx.x * blockDim.x + threadIdx.x;
    const int q   = no - 1 - tid;              // reversed mapping

    const float4* r4 = (const float4*)r;
    const int4*   d4 = (const int4*)dst;
    const int4*   s4 = (const int4*)src;

    if (q >= 0) {
        // front-batch ALL loads for 8 edges: 6x LDG.128 (r), 4x LDG.128
        // (indices), then 8 independent scattered coef gathers -> deep MLP.
        float rr[24];
        #pragma unroll
        for (int j = 0; j < 6; j++) {
            float4 V = __ldg(r4 + 6 * q + j);
            rr[4 * j + 0] = V.x; rr[4 * j + 1] = V.y;
            rr[4 * j + 2] = V.z; rr[4 * j + 3] = V.w;
        }
        int4 D0 = __ldg(d4 + 2 * q + 0);
        int4 D1 = __ldg(d4 + 2 * q + 1);
        int4 S0 = __ldg(s4 + 2 * q + 0);
        int4 S1 = __ldg(s4 + 2 * q + 1);
        int dd[8] = {D0.x, D0.y, D0.z, D0.w, D1.x, D1.y, D1.z, D1.w};
        int ss[8] = {S0.x, S0.y, S0.z, S0.w, S1.x, S1.y, S1.z, S1.w};
        float cc[8];
        #pragma unroll
        for (int k = 0; k < 8; k++) cc[k] = __ldg(&g_coef[dd[k]]);

        #pragma unroll
        for (int k = 0; k < 8; k++) {
            bwd_one(rr[3 * k], rr[3 * k + 1], rr[3 * k + 2],
                    dd[k], ss[k], cc[k], Ad, Ld, Ar, Lr);
        }
    }
    // tail edges (E not divisible by 8)
    int t = tid - no;
    int e = 8 * no + t;
    if (t >= 0 && e < E) {
        int d = __ldg(dst + e), s = __ldg(src + e);
        bwd_one(__ldg(r + 3 * e), __ldg(r + 3 * e + 1), __ldg(r + 3 * e + 2),
                d, s, __ldg(&g_coef[d]), Ad, Ld, Ar, Lr);
    }
}

// ---------------- finalize: pack output, self-clean scratch -----------------
// Four nodes per thread: 4x LDG.128 from g_f4, repack into 3x STG.128 to
// out+NGRAPH (16B-aligned: 128B base offset + 48B per group), 4x STG.128 zero.
__global__ void k_final(float* __restrict__ out, int N) {
    int t = blockIdx.x * blockDim.x + threadIdx.x;
    if (t < NGRAPH) {
        out[t] = g_enode[t] + g_eedge[t];
        g_enode[t] = 0.0f;
        g_eedge[t] = 0.0f;
    }
    int n0 = 4 * t;
    if (n0 + 3 < N) {
        float4 f0 = g_f4[n0 + 0];
        float4 f1 = g_f4[n0 + 1];
        float4 f2 = g_f4[n0 + 2];
        float4 f3 = g_f4[n0 + 3];
        float4* o4 = (float4*)(out + NGRAPH);
        o4[3 * t + 0] = make_float4(f0.x, f0.y, f0.z, f1.x);
        o4[3 * t + 1] = make_float4(f1.y, f1.z, f2.x, f2.y);
        o4[3 * t + 2] = make_float4(f2.z, f3.x, f3.y, f3.z);
        float4 z = make_float4(0.0f, 0.0f, 0.0f, 0.0f);
        g_f4[n0 + 0] = z; g_f4[n0 + 1] = z;
        g_f4[n0 + 2] = z; g_f4[n0 + 3] = z;
    } else if (n0 < N) {
        for (int n = n0; n < N; n++) {
            float4 f = g_f4[n];
            out[NGRAPH + 3 * n + 0] = f.x;
            out[NGRAPH + 3 * n + 1] = f.y;
            out[NGRAPH + 3 * n + 2] = f.z;
            g_f4[n] = make_float4(0.0f, 0.0f, 0.0f, 0.0f);
        }
    }
}

extern "C" void kernel_launch(void* const* d_in, const int* in_sizes, int n_in,
                              void* d_out, int out_size) {
    const float* r   = (const float*)d_in[0];
    const int*   src = (const int*)  d_in[1];
    const int*   dst = (const int*)  d_in[2];
    const int*   n2g = (const int*)  d_in[3];
    const float* pAd = (const float*)d_in[4];
    const float* pLd = (const float*)d_in[5];
    const float* pAr = (const float*)d_in[6];
    const float* pLr = (const float*)d_in[7];
    const float* pAe = (const float*)d_in[8];

    int E = in_sizes[1];
    int N = in_sizes[3];
    if (N > MAX_NODES) N = MAX_NODES;

    float* out = (float*)d_out;
    const int B = 256;

    // flat grids, one work item per thread (+ tail items)
    int itemsF = (E >> 2) + (E & 3);
    int itemsB = (E >> 3) + (E & 7);
    int gridE  = (itemsF + B - 1) / B;
    int gridB  = (itemsB + B - 1) / B;
    int gridN2 = ((N + 1) / 2 + B - 1) / B;
    int gridN4 = ((N + 3) / 4 + B - 1) / B;

    k_edge_fwd<<<gridE, B>>>(r, dst, pAd, pLd, pAr, pLr, E);
    k_node<<<gridN2, B>>>(n2g, pAe, N);
    k_edge_bwd<<<gridB, B>>>(r, src, dst, pAd, pLd, pAr, pLr, E);
    k_final<<<gridN4, B>>>(out, N);
}

// round 16
// speedup vs baseline: 1.0547x; 1.0547x over previous
#include <cuda_runtime.h>
#include <math.h>

#define MAX_NODES 100000
#define NGRAPH    32

// Self-cleaning scratch: zero at module load; each kernel that consumes a
// buffer re-zeroes it for the next graph replay.
static __device__ float2 g_nd[MAX_NODES];        // {density, rep} per node
static __device__ float  g_coef[MAX_NODES];      // dE/d(local_density) per node
static __device__ float4 g_f4[MAX_NODES];        // padded force accumulators
static __device__ float  g_enode[NGRAPH];
static __device__ float  g_eedge[NGRAPH];

__device__ __forceinline__ float softplus_f(float x) {
    return (x > 20.0f) ? x : log1pf(__expf(x));
}

__device__ __forceinline__ void red_add_v2(float2* p, float x, float y) {
    asm volatile("red.global.add.v2.f32 [%0], {%1, %2};"
                 :: "l"(p), "f"(x), "f"(y)
                 : "memory");
}

__device__ __forceinline__ void red_add_v4(float4* p, float x, float y, float z) {
    asm volatile("red.global.add.v4.f32 [%0], {%1, %2, %3, %4};"
                 :: "l"(p), "f"(x), "f"(y), "f"(z), "f"(0.0f)
                 : "memory");
}

// ---------------- forward: fused {density, rep} scatter ---------------------
// e_edge(g) factors through per-node rep sums, so rep rides in the same
// per-node vector RED as density (no per-edge graph atomic / n2g gather).
// LOCKED: 4 edges/thread (8/thread measured worse — RED-throughput bound).
__device__ __forceinline__ void fwd_one(float rx, float ry, float rz, int d,
                                        float Ad, float Ld, float Ar, float Lr) {
    float b = sqrtf(rx * rx + ry * ry + rz * rz);
    float dens = Ad * __expf(-Ld * b);
    float rep  = Ar * __expf(-Lr * b);
    red_add_v2(&g_nd[d], dens, rep);
}

__global__ void __launch_bounds__(256, 6)
k_edge_fwd(const float* __restrict__ r,
           const int*   __restrict__ dst,
           const float* __restrict__ pAd, const float* __restrict__ pLd,
           const float* __restrict__ pAr, const float* __restrict__ pLr,
           int E) {
    const float Ad = softplus_f(__ldg(pAd));
    const float Ld = softplus_f(__ldg(pLd));
    const float Ar = softplus_f(__ldg(pAr));
    const float Lr = softplus_f(__ldg(pLr));

    const int nq = E >> 2;
    const int q  = blockIdx.x * blockDim.x + threadIdx.x;

    const float4* r4 = (const float4*)r;
    const int4*   d4 = (const int4*)dst;

    if (q < nq) {
        float4 A = __ldg(r4 + 3 * q + 0);
        float4 B = __ldg(r4 + 3 * q + 1);
        float4 C = __ldg(r4 + 3 * q + 2);
        int4   D = __ldg(d4 + q);
        fwd_one(A.x, A.y, A.z, D.x, Ad, Ld, Ar, Lr);
        fwd_one(A.w, B.x, B.y, D.y, Ad, Ld, Ar, Lr);
        fwd_one(B.z, B.w, C.x, D.z, Ad, Ld, Ar, Lr);
        fwd_one(C.y, C.z, C.w, D.w, Ad, Ld, Ar, Lr);
    }
    // tail edges (E not divisible by 4) handled by first threads
    int t = q - nq;
    int e = 4 * nq + t;
    if (t >= 0 && e < E) {
        fwd_one(__ldg(r + 3 * e), __ldg(r + 3 * e + 1), __ldg(r + 3 * e + 2),
                __ldg(dst + e), Ad, Ld, Ar, Lr);
    }
}

// ---------------- node pass: embedding, grad coef, graph readouts -----------
// Two nodes per thread: one float4 load covers two g_nd entries, one float2
// store writes both coefs, and (node2graph is sorted) paired nodes nearly
// always share a graph -> combined smem atomic per pair.
__global__ void k_node(const int* __restrict__ n2g,
                       const float* __restrict__ pAe,
                       int N) {
    __shared__ float sF[NGRAPH];
    __shared__ float sR[NGRAPH];
    if (threadIdx.x < NGRAPH) { sF[threadIdx.x] = 0.0f; sR[threadIdx.x] = 0.0f; }
    __syncthreads();

    const float Ae = softplus_f(__ldg(pAe));
    int t  = blockIdx.x * blockDim.x + threadIdx.x;
    int i0 = 2 * t;
    if (i0 < N) {
        const float4* nd4 = (const float4*)g_nd;
        bool pair = (i0 + 1 < N);
        float4 v;
        if (pair) {
            v = nd4[t];                       // {ld0, rep0, ld1, rep1}
        } else {
            float2 s = g_nd[i0];
            v = make_float4(s.x, s.y, 0.0f, 0.0f);
        }

        float F0, c0, F1 = 0.0f, c1 = 0.0f;
        {
            float ld = v.x;
            if (ld > 1e-12f) {
                float rs = rsqrtf(ld);
                F0 = -Ae * ld * rs; c0 = -0.5f * Ae * rs;
            } else { F0 = -Ae * 1e-6f; c0 = 0.0f; }
        }
        if (pair) {
            float ld = v.z;
            if (ld > 1e-12f) {
                float rs = rsqrtf(ld);
                F1 = -Ae * ld * rs; c1 = -0.5f * Ae * rs;
            } else { F1 = -Ae * 1e-6f; c1 = 0.0f; }
        }

        // write both coefs with one 8B store; self-clean g_nd with one 16B store
        if (pair) {
            ((float2*)g_coef)[t] = make_float2(c0, c1);
            ((float4*)g_nd)[t]   = make_float4(0.0f, 0.0f, 0.0f, 0.0f);
        } else {
            g_coef[i0] = c0;
            g_nd[i0]   = make_float2(0.0f, 0.0f);
        }

        int g0 = __ldg(n2g + i0);
        int g1 = pair ? __ldg(n2g + i0 + 1) : g0;
        float rep1 = pair ? v.w : 0.0f;
        if (g0 == g1) {                        // common case: sorted n2g
            atomicAdd(&sF[g0], F0 + F1);
            atomicAdd(&sR[g0], v.y + rep1);
        } else {
            atomicAdd(&sF[g0], F0);
            atomicAdd(&sR[g0], v.y);
            atomicAdd(&sF[g1], F1);
            atomicAdd(&sR[g1], rep1);
        }
    }

    __syncthreads();
    if (threadIdx.x < NGRAPH) {
        atomicAdd(&g_enode[threadIdx.x], sF[threadIdx.x]);
        atomicAdd(&g_eedge[threadIdx.x], sR[threadIdx.x]);
    }
}

// ---------------- backward: force scatter -----------------------------------
__device__ __forceinline__ void bwd_one(float rx, float ry, float rz,
                                        int d, int s, float c,
                                        float Ad, float Ld, float Ar, float Lr) {
    float b2    = rx * rx + ry * ry + rz * rz;
    float inv_b = rsqrtf(b2);
    float b     = b2 * inv_b;
    float dens  = Ad * __expf(-Ld * b);
    float rep   = Ar * __expf(-Lr * b);
    float dEdb  = -c * Ld * dens - Lr * rep;
    float scale = dEdb * inv_b;
    float dx = scale * rx, dy = scale * ry, dz = scale * rz;
    red_add_v4(&g_f4[d], -dx, -dy, -dz);
    red_add_v4(&g_f4[s],  dx,  dy,  dz);
}

// NEW: 4 edges/thread (was 8). bwd is RED-throughput bound like fwd, and fwd
// measurably preferred 4/thread (more threads issuing REDs in parallel).
// Flat grid, block->edge mapping REVERSED so the first bwd wave touches the
// tail of r/src/dst that k_edge_fwd left in L2.
__global__ void __launch_bounds__(256, 6)
k_edge_bwd(const float* __restrict__ r,
           const int*   __restrict__ src,
           const int*   __restrict__ dst,
           const float* __restrict__ pAd, const float* __restrict__ pLd,
           const float* __restrict__ pAr, const float* __restrict__ pLr,
           int E) {
    const float Ad = softplus_f(__ldg(pAd));
    const float Ld = softplus_f(__ldg(pLd));
    const float Ar = softplus_f(__ldg(pAr));
    const float Lr = softplus_f(__ldg(pLr));

    const int nq  = E >> 2;
    const int tid = blockIdx.x * blockDim.x + threadIdx.x;
    const int q   = nq - 1 - tid;              // reversed mapping

    const float4* r4 = (const float4*)r;
    const int4*   d4 = (const int4*)dst;
    const int4*   s4 = (const int4*)src;

    if (q >= 0) {
        // front-batch ALL loads for 4 edges: 3x LDG.128 (r), 2x LDG.128
        // (indices), then 4 independent scattered coef gathers.
        float4 A = __ldg(r4 + 3 * q + 0);
        float4 B = __ldg(r4 + 3 * q + 1);
        float4 C = __ldg(r4 + 3 * q + 2);
        int4   D = __ldg(d4 + q);
        int4   S = __ldg(s4 + q);
        float c0 = __ldg(&g_coef[D.x]);
        float c1 = __ldg(&g_coef[D.y]);
        float c2 = __ldg(&g_coef[D.z]);
        float c3 = __ldg(&g_coef[D.w]);

        bwd_one(A.x, A.y, A.z, D.x, S.x, c0, Ad, Ld, Ar, Lr);
        bwd_one(A.w, B.x, B.y, D.y, S.y, c1, Ad, Ld, Ar, Lr);
        bwd_one(B.z, B.w, C.x, D.z, S.z, c2, Ad, Ld, Ar, Lr);
        bwd_one(C.y, C.z, C.w, D.w, S.w, c3, Ad, Ld, Ar, Lr);
    }
    // tail edges (E not divisible by 4)
    int t = tid - nq;
    int e = 4 * nq + t;
    if (t >= 0 && e < E) {
        int d = __ldg(dst + e), s = __ldg(src + e);
        bwd_one(__ldg(r + 3 * e), __ldg(r + 3 * e + 1), __ldg(r + 3 * e + 2),
                d, s, __ldg(&g_coef[d]), Ad, Ld, Ar, Lr);
    }
}

// ---------------- finalize: pack output, self-clean scratch -----------------
// One node per thread (best-measured in isolation: 4.9us; small kernels want
// threads, not vectors).
__global__ void k_final(float* __restrict__ out, int N) {
    int i = blockIdx.x * blockDim.x + threadIdx.x;
    if (i < NGRAPH) {
        out[i] = g_enode[i] + g_eedge[i];
        g_enode[i] = 0.0f;
        g_eedge[i] = 0.0f;
    }
    if (i < N) {
        float4 f = g_f4[i];
        out[NGRAPH + 3 * i + 0] = f.x;
        out[NGRAPH + 3 * i + 1] = f.y;
        out[NGRAPH + 3 * i + 2] = f.z;
        g_f4[i] = make_float4(0.0f, 0.0f, 0.0f, 0.0f);
    }
}

extern "C" void kernel_launch(void* const* d_in, const int* in_sizes, int n_in,
                              void* d_out, int out_size) {
    const float* r   = (const float*)d_in[0];
    const int*   src = (const int*)  d_in[1];
    const int*   dst = (const int*)  d_in[2];
    const int*   n2g = (const int*)  d_in[3];
    const float* pAd = (const float*)d_in[4];
    const float* pLd = (const float*)d_in[5];
    const float* pAr = (const float*)d_in[6];
    const float* pLr = (const float*)d_in[7];
    const float* pAe = (const float*)d_in[8];

    int E = in_sizes[1];
    int N = in_sizes[3];
    if (N > MAX_NODES) N = MAX_NODES;

    float* out = (float*)d_out;
    const int B = 256;

    // flat grids, one quad per thread (+ tail items)
    int itemsQ = (E >> 2) + (E & 3);
    int gridQ  = (itemsQ + B - 1) / B;
    int gridN  = (N + B - 1) / B;
    int gridN2 = ((N + 1) / 2 + B - 1) / B;

    k_edge_fwd<<<gridQ, B>>>(r, dst, pAd, pLd, pAr, pLr, E);
    k_node<<<gridN2, B>>>(n2g, pAe, N);
    k_edge_bwd<<<gridQ, B>>>(r, src, dst, pAd, pLd, pAr, pLr, E);
    k_final<<<gridN, B>>>(out, N);
}